// round 9
// baseline (speedup 1.0000x reference)
#include <cuda_runtime.h>

#define B_ 32
#define S_ 2048
#define F_ 768
#define H_ 8
#define KDIM_ (F_*H_)          // 6144
#define T_TILES_ 8             // 16-row tiles per block
#define CH_B_ 16               // chunks per batch (2048 / 128)
#define NPART_ (B_*CH_B_)      // 512 partial slabs

// Scratch (device globals; no runtime allocation)
__device__ float g_z[B_*H_];               // softmax denominators (atomic-accumulated)
__device__ float g_part[NPART_*KDIM_];     // per-block partial pooled slabs (50MB)
__device__ float g_pooled[B_*KDIM_];       // normalized pooled [b][f][h]

// ---------- packed f32x2 helpers ----------
__device__ __forceinline__ unsigned long long bcast2(float v) {
    unsigned int u = __float_as_uint(v);
    unsigned long long r;
    asm("mov.b64 %0, {%1, %1};" : "=l"(r) : "r"(u));
    return r;
}
__device__ __forceinline__ unsigned long long pack2(float a, float b) {
    unsigned long long r;
    asm("mov.b64 %0, {%1, %2};" : "=l"(r)
        : "r"(__float_as_uint(a)), "r"(__float_as_uint(b)));
    return r;
}
__device__ __forceinline__ void ffma2(unsigned long long &d, unsigned long long a, unsigned long long b) {
    asm("fma.rn.f32x2 %0, %1, %2, %0;" : "+l"(d) : "l"(a), "l"(b));
}
__device__ __forceinline__ unsigned long long fadd2(unsigned long long a, unsigned long long b) {
    unsigned long long r;
    asm("add.rn.f32x2 %0, %1, %2;" : "=l"(r) : "l"(a), "l"(b));
    return r;
}
__device__ __forceinline__ float2 unpack2(unsigned long long v) {
    unsigned int lo, hi;
    asm("mov.b64 {%0, %1}, %2;" : "=r"(lo), "=r"(hi) : "l"(v));
    return make_float2(__uint_as_float(lo), __uint_as_float(hi));
}

// ---------- cp.async helpers ----------
__device__ __forceinline__ unsigned int smem_u32(const void* p) {
    unsigned int a;
    asm("{ .reg .u64 t; cvta.to.shared.u64 t, %1; cvt.u32.u64 %0, t; }" : "=r"(a) : "l"(p));
    return a;
}
__device__ __forceinline__ void cp16(unsigned int dst, const void* src) {
    asm volatile("cp.async.cg.shared.global [%0], [%1], 16;" :: "r"(dst), "l"(src));
}
#define CP_COMMIT() asm volatile("cp.async.commit_group;" ::: "memory")
__device__ __forceinline__ void cp_wait_dyn(int n) {
    switch (n) {
    case 0:  asm volatile("cp.async.wait_group 0;"  ::: "memory"); break;
    case 1:  asm volatile("cp.async.wait_group 1;"  ::: "memory"); break;
    default: asm volatile("cp.async.wait_group 2;"  ::: "memory"); break;
    }
}

// ---------- K0a/K0b/K0c: init (split so k_fused is the 4th launch -> profiled) ----------
__global__ void __launch_bounds__(256) k_init_z() {
    g_z[threadIdx.x] = 0.f;
}
__global__ void __launch_bounds__(256) k_init_oa(const float* __restrict__ bout,
                                                 float* __restrict__ out) {
    int b = blockIdx.x;
    for (int i = threadIdx.x; i < F_; i += 256) out[b*F_ + i] = bout[i];
}
__global__ void __launch_bounds__(256) k_init_ob(const float* __restrict__ bout,
                                                 float* __restrict__ out) {
    int b = blockIdx.x + 16;
    for (int i = threadIdx.x; i < F_; i += 256) out[b*F_ + i] = bout[i];
}

// ---------- K_FUSED v4: half-tile double-buffered staging, coarse cp groups ----------
// grid (CH_B_, B_). Block: 128 rows = 8 tiles of 16 rows, staged as 8-row halves A/B.
// Per tile: phase1 (warp pid=warp>>1 rows pid*4..+3, heads hh=(warp&1)*4..+3; waits cp
//           groups at 4-chunk granularity), phase2-A -> restage A(t+1), phase2-B ->
//           restage B(t+1). A(t+1) staging latency hides under phase2-B + reduction.
#define XHALF_ (12*8*64*4)     // 24KB per half buffer
#define SMEM_FUSED_ (H_*F_*8 + 2*XHALF_ + 16*8*4 + 64)

__global__ void __launch_bounds__(256, 2) k_fused(const float* __restrict__ x,
                                                  const float* __restrict__ Wa,
                                                  const float* __restrict__ Wg,
                                                  const float* __restrict__ bg) {
    extern __shared__ __align__(16) unsigned char dyn[];
    unsigned long long* Wp = reinterpret_cast<unsigned long long*>(dyn);        // [6144] 48KB
    float* xa  = reinterpret_cast<float*>(dyn + H_*F_*8);                       // rows 0-7
    float* xb  = reinterpret_cast<float*>(dyn + H_*F_*8 + XHALF_);              // rows 8-15
    float* wsh = reinterpret_cast<float*>(dyn + H_*F_*8 + 2*XHALF_);            // [16][8]

    int tid = threadIdx.x, warp = tid >> 5, lane = tid & 31;
    int pid = warp >> 1, hh = (warp & 1) * 4;
    int b = blockIdx.y, chunk = blockIdx.x;
    int row00 = b*S_ + chunk*(16*T_TILES_);
    unsigned int xab = smem_u32(xa), xbb = smem_u32(xb);

    // stage an 8-row half: 3 cp groups of 4 f-chunks; thread covers row tid>>5
    auto stage_half = [&](unsigned int dstb, int grow0) {
        int r = tid >> 5, ln = tid & 31;
        const float* src = x + (size_t)(grow0 + r)*F_;
        int q = (ln & 15) * 4;
        #pragma unroll
        for (int g = 0; g < 3; g++) {
            int c1 = g*4 + (ln >> 4);
            int c2 = c1 + 2;
            cp16(dstb + (unsigned)((c1*8 + r)*64 + q)*4u, src + c1*64 + q);
            cp16(dstb + (unsigned)((c2*8 + r)*64 + q)*4u, src + c2*64 + q);
            CP_COMMIT();
        }
    };

    stage_half(xab, row00);                    // A_0
    stage_half(xbb, row00 + 8);                // B_0
    for (int i = tid; i < H_*F_; i += 256)     // W pack (L2-resident source)
        Wp[i] = pack2(Wa[i], Wg[i]);
    float bgv = bg[hh + (lane & 3)];

    const float* xsrc = (pid < 2) ? xa : xb;   // phase1 source half
    int rbase = (pid & 1) * 4;                 // rows rbase..rbase+3 within half

    unsigned long long acc[3][4];              // pooled accum: 3 f x 4 h-pairs
    #pragma unroll
    for (int i = 0; i < 3; i++)
        #pragma unroll
        for (int j = 0; j < 4; j++) acc[i][j] = 0ull;
    float zacc = 0.f;                          // lanes 0..3 meaningful (h = hh+lane)

    #pragma unroll 1
    for (int t = 0; t < T_TILES_; t++) {
        // ---- phase 1: rows pid*4..+3, heads hh..hh+3 ----
        {
            unsigned long long v[16];          // v[r*4 + h'] = (att, gate)
            #pragma unroll
            for (int i = 0; i < 16; i++) v[i] = 0ull;

            #pragma unroll
            for (int g = 0; g < 3; g++) {
                cp_wait_dyn(2 - g);            // A groups 0..2 + B groups 0..g arrived
                __syncthreads();
                #pragma unroll
                for (int cc = 0; cc < 4; cc++) {
                    int c = g*4 + cc;
                    float2 xv[4];
                    #pragma unroll
                    for (int r = 0; r < 4; r++)
                        xv[r] = *reinterpret_cast<const float2*>(
                            &xsrc[((c*8) + rbase + r)*64 + lane*2]);
                    unsigned long long xb2[8];
                    #pragma unroll
                    for (int r = 0; r < 4; r++) {
                        xb2[2*r]   = bcast2(xv[r].x);
                        xb2[2*r+1] = bcast2(xv[r].y);
                    }
                    int u = c*32 + lane;
                    #pragma unroll
                    for (int h = 0; h < 4; h++) {
                        ulonglong2 w = reinterpret_cast<const ulonglong2*>(Wp + (hh + h)*F_)[u];
                        #pragma unroll
                        for (int r = 0; r < 4; r++) {
                            ffma2(v[r*4 + h], xb2[2*r],   w.x);
                            ffma2(v[r*4 + h], xb2[2*r+1], w.y);
                        }
                    }
                }
            }

            // reduce 16 packed values across 32 lanes: value i -> lane i (0..15)
            #pragma unroll
            for (int i = 0; i < 16; i++)
                v[i] = fadd2(v[i], __shfl_xor_sync(0xffffffffu, v[i], 16));
            #pragma unroll
            for (int s = 8; s >= 1; s >>= 1) {
                bool up = (lane & s) != 0;
                #pragma unroll
                for (int i = 0; i < s; i++) {
                    unsigned long long send = up ? v[i] : v[i+s];
                    unsigned long long recv = __shfl_xor_sync(0xffffffffu, send, s);
                    unsigned long long keep = up ? v[i+s] : v[i];
                    v[i] = fadd2(keep, recv);
                }
            }

            float2 res = unpack2(v[0]);        // lane<16: r=lane>>2, h'=lane&3
            // no max-subtraction: logits ~ N(0,1); softmax shift-invariance (b_att cancels)
            float e = __expf(res.x);
            float wgt = e / (1.f + __expf(-(res.y + bgv)));
            if (lane < 16)
                wsh[(pid*4 + (lane >> 2))*8 + hh + (lane & 3)] = wgt;
            float ez = e;
            ez += __shfl_xor_sync(0xffffffffu, ez, 4);
            ez += __shfl_xor_sync(0xffffffffu, ez, 8);
            if (lane < 4) zacc += ez;
        }
        __syncthreads();                       // wsh ready

        int c0 = tid >> 6, q = tid & 63;
        // ---- phase 2A: rows 0..7 from xa ----
        #pragma unroll 4
        for (int sl = 0; sl < 8; sl++) {
            float x0 = xa[((c0    )*8 + sl)*64 + q];
            float x1 = xa[((c0 + 4)*8 + sl)*64 + q];
            float x2 = xa[((c0 + 8)*8 + sl)*64 + q];
            unsigned long long b0 = bcast2(x0), b1 = bcast2(x1), b2 = bcast2(x2);
            ulonglong2 w01 = *reinterpret_cast<const ulonglong2*>(&wsh[sl*8]);
            ulonglong2 w23 = *reinterpret_cast<const ulonglong2*>(&wsh[sl*8 + 4]);
            unsigned long long wp[4] = {w01.x, w01.y, w23.x, w23.y};
            #pragma unroll
            for (int hp = 0; hp < 4; hp++) {
                ffma2(acc[0][hp], b0, wp[hp]);
                ffma2(acc[1][hp], b1, wp[hp]);
                ffma2(acc[2][hp], b2, wp[hp]);
            }
        }
        __syncthreads();                       // all done reading xa
        if (t + 1 < T_TILES_) stage_half(xab, row00 + (t+1)*16);       // A(t+1)

        // ---- phase 2B: rows 8..15 from xb ----
        #pragma unroll 4
        for (int sl = 0; sl < 8; sl++) {
            float x0 = xb[((c0    )*8 + sl)*64 + q];
            float x1 = xb[((c0 + 4)*8 + sl)*64 + q];
            float x2 = xb[((c0 + 8)*8 + sl)*64 + q];
            unsigned long long b0 = bcast2(x0), b1 = bcast2(x1), b2 = bcast2(x2);
            ulonglong2 w01 = *reinterpret_cast<const ulonglong2*>(&wsh[(8+sl)*8]);
            ulonglong2 w23 = *reinterpret_cast<const ulonglong2*>(&wsh[(8+sl)*8 + 4]);
            unsigned long long wp[4] = {w01.x, w01.y, w23.x, w23.y};
            #pragma unroll
            for (int hp = 0; hp < 4; hp++) {
                ffma2(acc[0][hp], b0, wp[hp]);
                ffma2(acc[1][hp], b1, wp[hp]);
                ffma2(acc[2][hp], b2, wp[hp]);
            }
        }
        __syncthreads();                       // all done reading xb
        if (t + 1 < T_TILES_) stage_half(xbb, row00 + (t+1)*16 + 8);   // B(t+1)
    }

    if (lane < 4) atomicAdd(&g_z[b*8 + hh + lane], zacc);
    // write private partial slab (no atomics)
    unsigned long long* gp = reinterpret_cast<unsigned long long*>(
        g_part + (size_t)(b*CH_B_ + chunk)*KDIM_);
    #pragma unroll
    for (int fi = 0; fi < 3; fi++) {
        int f = tid + fi*256;
        #pragma unroll
        for (int hp = 0; hp < 4; hp++)
            gp[f*4 + hp] = acc[fi][hp];
    }
}

// ---------- K_NORM: g_pooled = (sum of 16 partial slabs) / Z ----------
__global__ void __launch_bounds__(256) k_norm() {
    __shared__ float iz[8];
    int b = blockIdx.x >> 1, half = blockIdx.x & 1;      // 64 blocks
    if (threadIdx.x < 8) iz[threadIdx.x] = 1.f / g_z[b*8 + threadIdx.x];
    __syncthreads();
    #pragma unroll
    for (int j = 0; j < 3; j++) {
        int idx4 = half*768 + j*256 + threadIdx.x;       // float4 index in batch slab
        float4 s = make_float4(0.f, 0.f, 0.f, 0.f);
        #pragma unroll
        for (int p = 0; p < CH_B_; p++) {
            float4 v = reinterpret_cast<const float4*>(
                g_part + (size_t)(b*CH_B_ + p)*KDIM_)[idx4];
            s.x += v.x; s.y += v.y; s.z += v.z; s.w += v.w;
        }
        int hb = (idx4 & 1) * 4;
        s.x *= iz[hb]; s.y *= iz[hb+1]; s.z *= iz[hb+2]; s.w *= iz[hb+3];
        reinterpret_cast<float4*>(g_pooled + (size_t)b*KDIM_)[idx4] = s;
    }
}

// ---------- K4: out += pooled @ Wout^T  (576 blocks, double-buffered, swizzled) ----------
#define NT_ 64       // output-column tile per block (grid.x = 12)
#define KT_ 128      // K range per block (grid.y = 48)
#define KSUB_ 64     // K staged per buffer (32 ull units)

__global__ void __launch_bounds__(256) k_out4(const float* __restrict__ Wout,
                                              float* __restrict__ out) {
    __shared__ unsigned long long ws[2][NT_][32];        // rotation-swizzled: phys=(k+col)&31
    __shared__ unsigned long long ps[2][32][32];
    int n0 = blockIdx.x * NT_;
    int k0h = blockIdx.y * (KT_/2);                      // in float2 units
    int cidx = threadIdx.x & 31;
    int bq   = threadIdx.x >> 5;
    const float2* W2 = reinterpret_cast<const float2*>(Wout);
    const float2* P2 = reinterpret_cast<const float2*>(g_pooled);

    int wc = threadIdx.x >> 5;
    int kq = threadIdx.x & 31;

    float2 rw[8], rp[4];
    #pragma unroll
    for (int s = 0; s < 8; s++)
        rw[s] = W2[(size_t)(n0 + wc + s*8)*(KDIM_/2) + k0h + kq];
    #pragma unroll
    for (int s = 0; s < 4; s++)
        rp[s] = P2[(size_t)(wc + s*8)*(KDIM_/2) + k0h + kq];
    #pragma unroll
    for (int s = 0; s < 8; s++)
        ws[0][wc + s*8][(kq + wc + s*8) & 31] = pack2(rw[s].x, rw[s].y);
    #pragma unroll
    for (int s = 0; s < 4; s++)
        ps[0][wc + s*8][kq] = pack2(rp[s].x, rp[s].y);
    __syncthreads();

    unsigned long long acc[4][2];
    #pragma unroll
    for (int r = 0; r < 4; r++) { acc[r][0] = 0ull; acc[r][1] = 0ull; }

    #pragma unroll
    for (int sub = 0; sub < KT_/KSUB_; sub++) {
        if (sub < KT_/KSUB_ - 1) {
            int kh = k0h + (sub+1)*32;
            #pragma unroll
            for (int s = 0; s < 8; s++)
                rw[s] = W2[(size_t)(n0 + wc + s*8)*(KDIM_/2) + kh + kq];
            #pragma unroll
            for (int s = 0; s < 4; s++)
                rp[s] = P2[(size_t)(wc + s*8)*(KDIM_/2) + kh + kq];
        }
        int buf = sub & 1;
        #pragma unroll 8
        for (int kk = 0; kk < 32; kk++) {
            int ph = (kk + cidx) & 31;
            unsigned long long wv0 = ws[buf][cidx][ph];
            unsigned long long wv1 = ws[buf][cidx + 32][ph];
            #pragma unroll
            for (int r = 0; r < 4; r++) {
                unsigned long long pv = ps[buf][bq*4 + r][kk];
                ffma2(acc[r][0], pv, wv0);
                ffma2(acc[r][1], pv, wv1);
            }
        }
        if (sub < KT_/KSUB_ - 1) {
            int nb = (sub + 1) & 1;
            #pragma unroll
            for (int s = 0; s < 8; s++)
                ws[nb][wc + s*8][(kq + wc + s*8) & 31] = pack2(rw[s].x, rw[s].y);
            #pragma unroll
            for (int s = 0; s < 4; s++)
                ps[nb][wc + s*8][kq] = pack2(rp[s].x, rp[s].y);
            __syncthreads();
        }
    }

    #pragma unroll
    for (int r = 0; r < 4; r++)
        #pragma unroll
        for (int c = 0; c < 2; c++) {
            float2 v = unpack2(acc[r][c]);
            atomicAdd(&out[(size_t)(bq*4 + r)*F_ + n0 + cidx + c*32], v.x + v.y);
        }
}

extern "C" void kernel_launch(void* const* d_in, const int* in_sizes, int n_in,
                              void* d_out, int out_size) {
    const float* x    = (const float*)d_in[0];   // [B,S,F]
    const float* Wa   = (const float*)d_in[1];   // [H,F]
    // d_in[2] = b_att: unused (softmax over s is shift-invariant per (b,h))
    const float* Wg   = (const float*)d_in[3];   // [H,F]
    const float* bg   = (const float*)d_in[4];   // [H]
    const float* Wout = (const float*)d_in[5];   // [F, H*F]
    const float* bout = (const float*)d_in[6];   // [F]
    float* out = (float*)d_out;                  // [B,F]

    static int smem_set = 0;
    if (!smem_set) {
        cudaFuncSetAttribute(k_fused, cudaFuncAttributeMaxDynamicSharedMemorySize,
                             SMEM_FUSED_);
        smem_set = 1;
    }

    k_init_z<<<1, 256>>>();
    k_init_oa<<<16, 256>>>(bout, out);
    k_init_ob<<<16, 256>>>(bout, out);
    k_fused<<<dim3(CH_B_, B_), 256, SMEM_FUSED_>>>(x, Wa, Wg, bg);   // 4th launch -> profiled
    k_norm<<<2*B_, 256>>>();
    k_out4<<<dim3(F_/NT_, KDIM_/KT_), 256>>>(Wout, out);
}